// round 2
// baseline (speedup 1.0000x reference)
#include <cuda_runtime.h>
#include <math_constants.h>

#define B_ 2
#define T_ 2048
#define E_ 2048
#define H_ 32
#define D_ 64
#define M_ (B_ * T_)          // 4096 rows for all projection GEMMs
#define SCALING 0.125f        // 64^-0.5

// Scratch (allocation-free rule: __device__ globals)
__device__ float g_Q[M_ * E_];
__device__ float g_K[M_ * E_];
__device__ float g_V[M_ * E_];
__device__ float g_C[M_ * E_];

// ---------------------------------------------------------------------------
// C[M,N] = alpha * (A[M,K] @ W[N,K]^T + bias[N]);  M=4096, N=K=2048
// 128x128 block, 256 threads, 8x8 per thread, BK=8.
// ---------------------------------------------------------------------------
__global__ __launch_bounds__(256) void gemm_nt_bias(
    const float* __restrict__ A, const float* __restrict__ W,
    const float* __restrict__ bias, float* __restrict__ C, float alpha)
{
    __shared__ float As[8][128];
    __shared__ float Ws[8][128];

    const int tid  = threadIdx.x;
    const int brow = blockIdx.y * 128;
    const int bcol = blockIdx.x * 128;

    const int lr = tid >> 1;          // 0..127 tile row
    const int lk = (tid & 1) << 2;    // 0 or 4 (k offset)
    const float* Ap = A + (size_t)(brow + lr) * E_ + lk;
    const float* Wp = W + (size_t)(bcol + lr) * E_ + lk;

    const int ty = tid >> 4;          // 0..15
    const int tx = tid & 15;          // 0..15

    float acc[8][8];
#pragma unroll
    for (int i = 0; i < 8; i++)
#pragma unroll
        for (int j = 0; j < 8; j++) acc[i][j] = 0.f;

    for (int k0 = 0; k0 < E_; k0 += 8) {
        float4 av = *(const float4*)(Ap + k0);
        float4 wv = *(const float4*)(Wp + k0);
        __syncthreads();
        As[lk + 0][lr] = av.x; As[lk + 1][lr] = av.y;
        As[lk + 2][lr] = av.z; As[lk + 3][lr] = av.w;
        Ws[lk + 0][lr] = wv.x; Ws[lk + 1][lr] = wv.y;
        Ws[lk + 2][lr] = wv.z; Ws[lk + 3][lr] = wv.w;
        __syncthreads();

#pragma unroll
        for (int kk = 0; kk < 8; kk++) {
            float4 a0 = *(const float4*)&As[kk][ty * 8];
            float4 a1 = *(const float4*)&As[kk][ty * 8 + 4];
            float4 b0 = *(const float4*)&Ws[kk][tx * 8];
            float4 b1 = *(const float4*)&Ws[kk][tx * 8 + 4];
            float a[8] = {a0.x, a0.y, a0.z, a0.w, a1.x, a1.y, a1.z, a1.w};
            float b[8] = {b0.x, b0.y, b0.z, b0.w, b1.x, b1.y, b1.z, b1.w};
#pragma unroll
            for (int i = 0; i < 8; i++)
#pragma unroll
                for (int j = 0; j < 8; j++)
                    acc[i][j] = fmaf(a[i], b[j], acc[i][j]);
        }
    }

#pragma unroll
    for (int i = 0; i < 8; i++) {
        const size_t row = (size_t)(brow + ty * 8 + i);
#pragma unroll
        for (int j = 0; j < 8; j += 4) {
            const int col = bcol + tx * 8 + j;
            float4 o;
            o.x = alpha * (acc[i][j + 0] + bias[col + 0]);
            o.y = alpha * (acc[i][j + 1] + bias[col + 1]);
            o.z = alpha * (acc[i][j + 2] + bias[col + 2]);
            o.w = alpha * (acc[i][j + 3] + bias[col + 3]);
            *(float4*)&C[row * E_ + col] = o;
        }
    }
}

// ---------------------------------------------------------------------------
// Flash-style causal attention. One block per (b, h, 64-row q tile).
// 256 threads = 16x16; 4x4 per thread on 64x64 tiles. Online softmax.
// Smem: qs (d-major) + kv union (K d-major, then V c-major) + P tile = 48 KB.
// ---------------------------------------------------------------------------
__global__ __launch_bounds__(256) void attn_kernel(
    const float* __restrict__ Q, const float* __restrict__ K,
    const float* __restrict__ V, float* __restrict__ Cx)
{
    __shared__ float qs[64 * 64];   // qs[d*64 + r]
    __shared__ float kv[64 * 64];   // phase 1: ks[d*64+c]; phase 2: vs[c*64+d]
    __shared__ float ps[64 * 64];   // ps[c*64 + r]

    const int tid = threadIdx.x;
    const int qt  = blockIdx.x;     // 0..31
    const int bh  = blockIdx.y;     // 0..63
    const int b   = bh >> 5;
    const int h   = bh & 31;
    const int ty  = tid >> 4, tx = tid & 15;
    const int r0  = ty * 4;         // rows of s/acc handled by this thread
    const int c0  = tx * 4;         // cols of s (k-index) AND dims of acc

    const size_t headoff = (size_t)h * D_;
    const float* Qb = Q + (size_t)(b * T_ + qt * 64) * E_ + headoff;
    const float* Kb = K + (size_t)(b * T_) * E_ + headoff;
    const float* Vb = V + (size_t)(b * T_) * E_ + headoff;

    // load Q tile transposed (d-major)
    {
        const int tok = tid >> 2;
        const int db  = (tid & 3) * 16;
        const float* src = Qb + (size_t)tok * E_ + db;
#pragma unroll
        for (int q = 0; q < 4; q++) {
            float4 v4 = *(const float4*)(src + q * 4);
            const int d = db + q * 4;
            qs[(d + 0) * 64 + tok] = v4.x; qs[(d + 1) * 64 + tok] = v4.y;
            qs[(d + 2) * 64 + tok] = v4.z; qs[(d + 3) * 64 + tok] = v4.w;
        }
    }

    float acc[4][4];
#pragma unroll
    for (int i = 0; i < 4; i++)
#pragma unroll
        for (int j = 0; j < 4; j++) acc[i][j] = 0.f;
    float mprev[4], lsum[4];
#pragma unroll
    for (int i = 0; i < 4; i++) { mprev[i] = -CUDART_INF_F; lsum[i] = 0.f; }

    for (int jt = 0; jt <= qt; jt++) {
        __syncthreads();  // prior-iter readers of kv/ps are done; qs visible
        // load K tile transposed (d-major) into kv
        {
            const int tok = tid >> 2;
            const int db  = (tid & 3) * 16;
            const float* src = Kb + (size_t)(jt * 64 + tok) * E_ + db;
#pragma unroll
            for (int q = 0; q < 4; q++) {
                float4 v4 = *(const float4*)(src + q * 4);
                const int d = db + q * 4;
                kv[(d + 0) * 64 + tok] = v4.x; kv[(d + 1) * 64 + tok] = v4.y;
                kv[(d + 2) * 64 + tok] = v4.z; kv[(d + 3) * 64 + tok] = v4.w;
            }
        }
        __syncthreads();

        // s = q @ k^T  (4x4 per thread)
        float s[4][4];
#pragma unroll
        for (int i = 0; i < 4; i++)
#pragma unroll
            for (int j = 0; j < 4; j++) s[i][j] = 0.f;
#pragma unroll 8
        for (int d = 0; d < 64; d++) {
            float4 a4 = *(const float4*)&qs[d * 64 + r0];
            float4 b4 = *(const float4*)&kv[d * 64 + c0];
            float a[4] = {a4.x, a4.y, a4.z, a4.w};
            float bb[4] = {b4.x, b4.y, b4.z, b4.w};
#pragma unroll
            for (int i = 0; i < 4; i++)
#pragma unroll
                for (int j = 0; j < 4; j++)
                    s[i][j] = fmaf(a[i], bb[j], s[i][j]);
        }

        // causal mask only on the diagonal tile
        if (jt == qt) {
#pragma unroll
            for (int i = 0; i < 4; i++)
#pragma unroll
                for (int j = 0; j < 4; j++)
                    if (c0 + j > r0 + i) s[i][j] = -CUDART_INF_F;
        }

        // online softmax: row max + scale
        float mnew[4], scl[4];
#pragma unroll
        for (int i = 0; i < 4; i++) {
            float mx = fmaxf(fmaxf(s[i][0], s[i][1]), fmaxf(s[i][2], s[i][3]));
#pragma unroll
            for (int off = 8; off >= 1; off >>= 1)
                mx = fmaxf(mx, __shfl_xor_sync(0xffffffffu, mx, off));
            mnew[i] = fmaxf(mprev[i], mx);
            scl[i]  = __expf(mprev[i] - mnew[i]);   // first iter: exp(-inf)=0
        }
        // p = exp(s - m), row sums, l update
#pragma unroll
        for (int i = 0; i < 4; i++) {
            float rs = 0.f;
#pragma unroll
            for (int j = 0; j < 4; j++) {
                float p = __expf(s[i][j] - mnew[i]);
                s[i][j] = p;
                rs += p;
            }
#pragma unroll
            for (int off = 8; off >= 1; off >>= 1)
                rs += __shfl_xor_sync(0xffffffffu, rs, off);
            lsum[i]  = lsum[i] * scl[i] + rs;
            mprev[i] = mnew[i];
        }
        // stage P to smem (c-major)
#pragma unroll
        for (int i = 0; i < 4; i++)
#pragma unroll
            for (int j = 0; j < 4; j++)
                ps[(c0 + j) * 64 + (r0 + i)] = s[i][j];
        __syncthreads();  // all kv(K) reads + ps writes complete

        // load V tile (c-major) into kv
        {
            const int tok = tid >> 2;
            const int db  = (tid & 3) * 16;
            const float* src = Vb + (size_t)(jt * 64 + tok) * E_ + db;
#pragma unroll
            for (int q = 0; q < 4; q++)
                *(float4*)&kv[tok * 64 + db + q * 4] = *(const float4*)(src + q * 4);
        }
        __syncthreads();

        // acc = acc*scale + P @ V
#pragma unroll
        for (int i = 0; i < 4; i++)
#pragma unroll
            for (int j = 0; j < 4; j++) acc[i][j] *= scl[i];
#pragma unroll 8
        for (int c = 0; c < 64; c++) {
            float4 pa = *(const float4*)&ps[c * 64 + r0];
            float4 vb = *(const float4*)&kv[c * 64 + c0];
            float p[4] = {pa.x, pa.y, pa.z, pa.w};
            float v[4] = {vb.x, vb.y, vb.z, vb.w};
#pragma unroll
            for (int i = 0; i < 4; i++)
#pragma unroll
                for (int j = 0; j < 4; j++)
                    acc[i][j] = fmaf(p[i], v[j], acc[i][j]);
        }
    }

    // epilogue: ctx[b, t, h*64+d] = acc / l
    float* Cb = Cx + (size_t)(b * T_ + qt * 64) * E_ + headoff;
#pragma unroll
    for (int i = 0; i < 4; i++) {
        const float inv = 1.f / lsum[i];
        float4 o;
        o.x = acc[i][0] * inv; o.y = acc[i][1] * inv;
        o.z = acc[i][2] * inv; o.w = acc[i][3] * inv;
        *(float4*)&Cb[(size_t)(r0 + i) * E_ + c0] = o;
    }
}

// ---------------------------------------------------------------------------
extern "C" void kernel_launch(void* const* d_in, const int* in_sizes, int n_in,
                              void* d_out, int out_size)
{
    const float* X  = (const float*)d_in[0];
    const float* Wq = (const float*)d_in[1];
    const float* bq = (const float*)d_in[2];
    const float* Wk = (const float*)d_in[3];
    const float* bk = (const float*)d_in[4];
    const float* Wv = (const float*)d_in[5];
    const float* bv = (const float*)d_in[6];
    const float* Wo = (const float*)d_in[7];
    const float* bo = (const float*)d_in[8];
    float* out = (float*)d_out;

    float *Qp, *Kp, *Vp, *Cp;
    cudaGetSymbolAddress((void**)&Qp, g_Q);
    cudaGetSymbolAddress((void**)&Kp, g_K);
    cudaGetSymbolAddress((void**)&Vp, g_V);
    cudaGetSymbolAddress((void**)&Cp, g_C);

    dim3 gemm_grid(E_ / 128, M_ / 128);   // (16, 32)
    gemm_nt_bias<<<gemm_grid, 256>>>(X, Wq, bq, Qp, SCALING);
    gemm_nt_bias<<<gemm_grid, 256>>>(X, Wk, bk, Kp, 1.0f);
    gemm_nt_bias<<<gemm_grid, 256>>>(X, Wv, bv, Vp, 1.0f);

    dim3 attn_grid(T_ / 64, B_ * H_);     // (32, 64)
    attn_kernel<<<attn_grid, 256>>>(Qp, Kp, Vp, Cp);

    gemm_nt_bias<<<gemm_grid, 256>>>(Cp, Wo, bo, out, 1.0f);
}

// round 5
// speedup vs baseline: 1.7326x; 1.7326x over previous
#include <cuda_runtime.h>
#include <cuda_bf16.h>
#include <math_constants.h>
#include <cstdint>

#define B_ 2
#define T_ 2048
#define E_ 2048
#define H_ 32
#define D_ 64
#define M_ (B_ * T_)
#define SCALING 0.125f

// ---------------- scratch (__device__ globals; allocation-free rule) --------
__device__ float g_Q[M_ * E_];
__device__ float g_K[M_ * E_];
__device__ float g_V[M_ * E_];
__device__ float g_C[M_ * E_];
__device__ __nv_bfloat16 g_Ahi[M_ * E_];   // split of X, later of ctx
__device__ __nv_bfloat16 g_Alo[M_ * E_];
__device__ __nv_bfloat16 g_Whi[E_ * E_];   // split of current weight
__device__ __nv_bfloat16 g_Wlo[E_ * E_];

// ---------------- helpers (portable sm_100: cp.async + ldmatrix + mma.sync) -
__device__ __forceinline__ uint32_t smem_u32(const void* p) {
    uint32_t a;
    asm("{ .reg .u64 t; cvta.to.shared.u64 t, %1; cvt.u32.u64 %0, t; }" : "=r"(a) : "l"(p));
    return a;
}
__device__ __forceinline__ void cp16(uint32_t dst, const void* src) {
    asm volatile("cp.async.cg.shared.global [%0], [%1], 16;" :: "r"(dst), "l"(src));
}
__device__ __forceinline__ void cp_commit() {
    asm volatile("cp.async.commit_group;" ::: "memory");
}
template <int N>
__device__ __forceinline__ void cp_wait() {
    asm volatile("cp.async.wait_group %0;" :: "n"(N) : "memory");
}
__device__ __forceinline__ void ldm_x4(uint32_t* d, uint32_t addr) {
    asm volatile("ldmatrix.sync.aligned.m8n8.x4.shared.b16 {%0,%1,%2,%3}, [%4];"
                 : "=r"(d[0]), "=r"(d[1]), "=r"(d[2]), "=r"(d[3]) : "r"(addr));
}
__device__ __forceinline__ void mma16816(float* c, const uint32_t* a, uint32_t b0, uint32_t b1) {
    asm volatile("mma.sync.aligned.m16n8k16.row.col.f32.bf16.bf16.f32 "
                 "{%0,%1,%2,%3}, {%4,%5,%6,%7}, {%8,%9}, {%0,%1,%2,%3};"
                 : "+f"(c[0]), "+f"(c[1]), "+f"(c[2]), "+f"(c[3])
                 : "r"(a[0]), "r"(a[1]), "r"(a[2]), "r"(a[3]), "r"(b0), "r"(b1));
}

// swizzled offset inside a 128x32-bf16 tile (64B rows, 4x16B chunks per row).
// Every ldmatrix phase (8 rows, fixed c) hits 8 distinct 16B bank-groups.
__device__ __forceinline__ uint32_t tile_off(int r, int c) {
    return (uint32_t)(r * 64 + ((c ^ ((r >> 1) & 3)) << 4));
}

// ---------------------------------------------------------------------------
// split x (fp32) -> hi + lo (bf16 each)
// ---------------------------------------------------------------------------
__global__ __launch_bounds__(256) void split_fp32(
    const float* __restrict__ x, __nv_bfloat16* __restrict__ hi,
    __nv_bfloat16* __restrict__ lo, int n4)
{
    int i = blockIdx.x * 256 + threadIdx.x;
    if (i >= n4) return;
    float4 v = ((const float4*)x)[i];
    __nv_bfloat16 h[4], l[4];
    float f[4] = {v.x, v.y, v.z, v.w};
#pragma unroll
    for (int j = 0; j < 4; j++) {
        h[j] = __float2bfloat16(f[j]);
        l[j] = __float2bfloat16(f[j] - __bfloat162float(h[j]));
    }
    ((ushort4*)hi)[i] = make_ushort4(*(unsigned short*)&h[0], *(unsigned short*)&h[1],
                                     *(unsigned short*)&h[2], *(unsigned short*)&h[3]);
    ((ushort4*)lo)[i] = make_ushort4(*(unsigned short*)&l[0], *(unsigned short*)&l[1],
                                     *(unsigned short*)&l[2], *(unsigned short*)&l[3]);
}

// ---------------------------------------------------------------------------
// bf16x3 split GEMM via mma.sync: C[M,N] = alpha*(A@W^T + bias)
// CTA 128x128, BK=32, 8 warps (warp tile 32x64), cp.async double buffer.
// Stage (32KB): Ahi 8K | Alo 8K | Whi 8K | Wlo 8K
// ---------------------------------------------------------------------------
#define STAGE 32768
#define SMEM_GEMM (2 * STAGE)
#define NCHUNK (E_ / 32)

__global__ __launch_bounds__(256, 1) void gemm_tc(
    const __nv_bfloat16* __restrict__ Ahi, const __nv_bfloat16* __restrict__ Alo,
    const __nv_bfloat16* __restrict__ Whi, const __nv_bfloat16* __restrict__ Wlo,
    const float* __restrict__ bias, float* __restrict__ C, float alpha)
{
    extern __shared__ __align__(1024) char smem[];
    const uint32_t su = smem_u32(smem);
    const int tid = threadIdx.x, wid = tid >> 5, lane = tid & 31;
    const int brow = blockIdx.y * 128, bcol = blockIdx.x * 128;
    const int wm = wid & 3;        // warp row block (32 rows)
    const int wn = wid >> 2;       // warp col block (64 cols)

    float acc[2][8][4];
#pragma unroll
    for (int mt = 0; mt < 2; mt++)
#pragma unroll
        for (int j = 0; j < 8; j++)
#pragma unroll
            for (int q = 0; q < 4; q++) acc[mt][j][q] = 0.f;

    auto load_chunk = [&](int k0, int s) {
        const uint32_t base = su + s * STAGE;
#pragma unroll
        for (int it = 0; it < 2; it++) {
            int idx = tid + it * 256;          // 0..511
            int r = idx >> 2, c = idx & 3;
            uint32_t off = tile_off(r, c);
            size_t ga = (size_t)(brow + r) * E_ + k0 + c * 8;
            size_t gw = (size_t)(bcol + r) * E_ + k0 + c * 8;
            cp16(base +         off, Ahi + ga);
            cp16(base +  8192 + off, Alo + ga);
            cp16(base + 16384 + off, Whi + gw);
            cp16(base + 24576 + off, Wlo + gw);
        }
    };

    load_chunk(0, 0);
    cp_commit();

    for (int k = 0; k < NCHUNK; k++) {
        const int s = k & 1;
        if (k + 1 < NCHUNK) {
            load_chunk((k + 1) * 32, s ^ 1);
            cp_commit();
            cp_wait<1>();
        } else {
            cp_wait<0>();
        }
        __syncthreads();

        const uint32_t bA_hi = su + s * STAGE;
        const uint32_t bA_lo = bA_hi + 8192;
        const uint32_t bW_hi = bA_hi + 16384;
        const uint32_t bW_lo = bA_hi + 24576;

#pragma unroll
        for (int ks = 0; ks < 2; ks++) {
            const int cc = ks * 2 + (lane >> 4);
            uint32_t ah[2][4], al[2][4];
#pragma unroll
            for (int mt = 0; mt < 2; mt++) {
                const int r = wm * 32 + mt * 16 + (lane & 15);
                const uint32_t off = tile_off(r, cc);
                ldm_x4(ah[mt], bA_hi + off);
                ldm_x4(al[mt], bA_lo + off);
            }
            uint32_t bh[4][4], bl[4][4];
#pragma unroll
            for (int nb = 0; nb < 4; nb++) {
                const int r = wn * 64 + nb * 16 + (lane & 15);
                const uint32_t off = tile_off(r, cc);
                ldm_x4(bh[nb], bW_hi + off);
                ldm_x4(bl[nb], bW_lo + off);
            }
#pragma unroll
            for (int mt = 0; mt < 2; mt++)
#pragma unroll
                for (int j = 0; j < 8; j++) {
                    const int nb = j >> 1, sel = j & 1;
                    mma16816(acc[mt][j], ah[mt], bh[nb][sel], bh[nb][sel + 2]);  // hi*hi
                    mma16816(acc[mt][j], ah[mt], bl[nb][sel], bl[nb][sel + 2]);  // hi*lo
                    mma16816(acc[mt][j], al[mt], bh[nb][sel], bh[nb][sel + 2]);  // lo*hi
                }
        }
        __syncthreads();
    }

    // epilogue: alpha*(acc + bias)
#pragma unroll
    for (int mt = 0; mt < 2; mt++) {
        const int r0 = brow + wm * 32 + mt * 16 + (lane >> 2);
#pragma unroll
        for (int j = 0; j < 8; j++) {
            const int col = bcol + wn * 64 + j * 8 + (lane & 3) * 2;
            const float bx = bias[col], by = bias[col + 1];
            float2 o0, o1;
            o0.x = alpha * (acc[mt][j][0] + bx);
            o0.y = alpha * (acc[mt][j][1] + by);
            o1.x = alpha * (acc[mt][j][2] + bx);
            o1.y = alpha * (acc[mt][j][3] + by);
            *(float2*)&C[(size_t)r0 * E_ + col]       = o0;
            *(float2*)&C[(size_t)(r0 + 8) * E_ + col] = o1;
        }
    }
}

// ---------------------------------------------------------------------------
// Flash-style causal attention (unchanged: fp32, rel_err 7e-7 baseline)
// ---------------------------------------------------------------------------
__global__ __launch_bounds__(256) void attn_kernel(
    const float* __restrict__ Q, const float* __restrict__ K,
    const float* __restrict__ V, float* __restrict__ Cx)
{
    __shared__ float qs[64 * 64];
    __shared__ float kv[64 * 64];
    __shared__ float ps[64 * 64];

    const int tid = threadIdx.x;
    const int qt  = blockIdx.x;
    const int bh  = blockIdx.y;
    const int b   = bh >> 5;
    const int h   = bh & 31;
    const int ty  = tid >> 4, tx = tid & 15;
    const int r0  = ty * 4;
    const int c0  = tx * 4;

    const size_t headoff = (size_t)h * D_;
    const float* Qb = Q + (size_t)(b * T_ + qt * 64) * E_ + headoff;
    const float* Kb = K + (size_t)(b * T_) * E_ + headoff;
    const float* Vb = V + (size_t)(b * T_) * E_ + headoff;

    {
        const int tok = tid >> 2;
        const int db  = (tid & 3) * 16;
        const float* src = Qb + (size_t)tok * E_ + db;
#pragma unroll
        for (int q = 0; q < 4; q++) {
            float4 v4 = *(const float4*)(src + q * 4);
            const int d = db + q * 4;
            qs[(d + 0) * 64 + tok] = v4.x; qs[(d + 1) * 64 + tok] = v4.y;
            qs[(d + 2) * 64 + tok] = v4.z; qs[(d + 3) * 64 + tok] = v4.w;
        }
    }

    float acc[4][4];
#pragma unroll
    for (int i = 0; i < 4; i++)
#pragma unroll
        for (int j = 0; j < 4; j++) acc[i][j] = 0.f;
    float mprev[4], lsum[4];
#pragma unroll
    for (int i = 0; i < 4; i++) { mprev[i] = -CUDART_INF_F; lsum[i] = 0.f; }

    for (int jt = 0; jt <= qt; jt++) {
        __syncthreads();
        {
            const int tok = tid >> 2;
            const int db  = (tid & 3) * 16;
            const float* src = Kb + (size_t)(jt * 64 + tok) * E_ + db;
#pragma unroll
            for (int q = 0; q < 4; q++) {
                float4 v4 = *(const float4*)(src + q * 4);
                const int d = db + q * 4;
                kv[(d + 0) * 64 + tok] = v4.x; kv[(d + 1) * 64 + tok] = v4.y;
                kv[(d + 2) * 64 + tok] = v4.z; kv[(d + 3) * 64 + tok] = v4.w;
            }
        }
        __syncthreads();

        float s[4][4];
#pragma unroll
        for (int i = 0; i < 4; i++)
#pragma unroll
            for (int j = 0; j < 4; j++) s[i][j] = 0.f;
#pragma unroll 8
        for (int d = 0; d < 64; d++) {
            float4 a4 = *(const float4*)&qs[d * 64 + r0];
            float4 b4 = *(const float4*)&kv[d * 64 + c0];
            float a[4] = {a4.x, a4.y, a4.z, a4.w};
            float bb[4] = {b4.x, b4.y, b4.z, b4.w};
#pragma unroll
            for (int i = 0; i < 4; i++)
#pragma unroll
                for (int j = 0; j < 4; j++)
                    s[i][j] = fmaf(a[i], bb[j], s[i][j]);
        }

        if (jt == qt) {
#pragma unroll
            for (int i = 0; i < 4; i++)
#pragma unroll
                for (int j = 0; j < 4; j++)
                    if (c0 + j > r0 + i) s[i][j] = -CUDART_INF_F;
        }

        float mnew[4], scl[4];
#pragma unroll
        for (int i = 0; i < 4; i++) {
            float mx = fmaxf(fmaxf(s[i][0], s[i][1]), fmaxf(s[i][2], s[i][3]));
#pragma unroll
            for (int off = 8; off >= 1; off >>= 1)
                mx = fmaxf(mx, __shfl_xor_sync(0xffffffffu, mx, off));
            mnew[i] = fmaxf(mprev[i], mx);
            scl[i]  = __expf(mprev[i] - mnew[i]);
        }
#pragma unroll
        for (int i = 0; i < 4; i++) {
            float rs = 0.f;
#pragma unroll
            for (int j = 0; j < 4; j++) {
                float p = __expf(s[i][j] - mnew[i]);
                s[i][j] = p;
                rs += p;
            }
#pragma unroll
            for (int off = 8; off >= 1; off >>= 1)
                rs += __shfl_xor_sync(0xffffffffu, rs, off);
            lsum[i]  = lsum[i] * scl[i] + rs;
            mprev[i] = mnew[i];
        }
#pragma unroll
        for (int i = 0; i < 4; i++)
#pragma unroll
            for (int j = 0; j < 4; j++)
                ps[(c0 + j) * 64 + (r0 + i)] = s[i][j];
        __syncthreads();

        {
            const int tok = tid >> 2;
            const int db  = (tid & 3) * 16;
            const float* src = Vb + (size_t)(jt * 64 + tok) * E_ + db;
#pragma unroll
            for (int q = 0; q < 4; q++)
                *(float4*)&kv[tok * 64 + db + q * 4] = *(const float4*)(src + q * 4);
        }
        __syncthreads();

#pragma unroll
        for (int i = 0; i < 4; i++)
#pragma unroll
            for (int j = 0; j < 4; j++) acc[i][j] *= scl[i];
#pragma unroll 8
        for (int c = 0; c < 64; c++) {
            float4 pa = *(const float4*)&ps[c * 64 + r0];
            float4 vb = *(const float4*)&kv[c * 64 + c0];
            float p[4] = {pa.x, pa.y, pa.z, pa.w};
            float v[4] = {vb.x, vb.y, vb.z, vb.w};
#pragma unroll
            for (int i = 0; i < 4; i++)
#pragma unroll
                for (int j = 0; j < 4; j++)
                    acc[i][j] = fmaf(p[i], v[j], acc[i][j]);
        }
    }

    float* Cb = Cx + (size_t)(b * T_ + qt * 64) * E_ + headoff;
#pragma unroll
    for (int i = 0; i < 4; i++) {
        const float inv = 1.f / lsum[i];
        float4 o;
        o.x = acc[i][0] * inv; o.y = acc[i][1] * inv;
        o.z = acc[i][2] * inv; o.w = acc[i][3] * inv;
        *(float4*)&Cb[(size_t)(r0 + i) * E_ + c0] = o;
    }
}

// ---------------------------------------------------------------------------
extern "C" void kernel_launch(void* const* d_in, const int* in_sizes, int n_in,
                              void* d_out, int out_size)
{
    const float* X  = (const float*)d_in[0];
    const float* Wq = (const float*)d_in[1];
    const float* bq = (const float*)d_in[2];
    const float* Wk = (const float*)d_in[3];
    const float* bk = (const float*)d_in[4];
    const float* Wv = (const float*)d_in[5];
    const float* bv = (const float*)d_in[6];
    const float* Wo = (const float*)d_in[7];
    const float* bo = (const float*)d_in[8];
    float* out = (float*)d_out;

    float *Qp, *Kp, *Vp, *Cp;
    __nv_bfloat16 *Ahi, *Alo, *Whi, *Wlo;
    cudaGetSymbolAddress((void**)&Qp, g_Q);
    cudaGetSymbolAddress((void**)&Kp, g_K);
    cudaGetSymbolAddress((void**)&Vp, g_V);
    cudaGetSymbolAddress((void**)&Cp, g_C);
    cudaGetSymbolAddress((void**)&Ahi, g_Ahi);
    cudaGetSymbolAddress((void**)&Alo, g_Alo);
    cudaGetSymbolAddress((void**)&Whi, g_Whi);
    cudaGetSymbolAddress((void**)&Wlo, g_Wlo);

    cudaFuncSetAttribute(gemm_tc, cudaFuncAttributeMaxDynamicSharedMemorySize, SMEM_GEMM);

    const int nX4 = (M_ * E_) / 4;
    const int nW4 = (E_ * E_) / 4;
    dim3 gg(E_ / 128, M_ / 128);     // (16, 32) = 512 CTAs

    split_fp32<<<(nX4 + 255) / 256, 256>>>(X, Ahi, Alo, nX4);

    split_fp32<<<(nW4 + 255) / 256, 256>>>(Wq, Whi, Wlo, nW4);
    gemm_tc<<<gg, 256, SMEM_GEMM>>>(Ahi, Alo, Whi, Wlo, bq, Qp, SCALING);

    split_fp32<<<(nW4 + 255) / 256, 256>>>(Wk, Whi, Wlo, nW4);
    gemm_tc<<<gg, 256, SMEM_GEMM>>>(Ahi, Alo, Whi, Wlo, bk, Kp, 1.0f);

    split_fp32<<<(nW4 + 255) / 256, 256>>>(Wv, Whi, Wlo, nW4);
    gemm_tc<<<gg, 256, SMEM_GEMM>>>(Ahi, Alo, Whi, Wlo, bv, Vp, 1.0f);

    dim3 ag(T_ / 64, B_ * H_);
    attn_kernel<<<ag, 256>>>(Qp, Kp, Vp, Cp);

    split_fp32<<<(nX4 + 255) / 256, 256>>>(Cp, Ahi, Alo, nX4);
    split_fp32<<<(nW4 + 255) / 256, 256>>>(Wo, Whi, Wlo, nW4);
    gemm_tc<<<gg, 256, SMEM_GEMM>>>(Ahi, Alo, Whi, Wlo, bo, out, 1.0f);
}

// round 6
// speedup vs baseline: 2.8916x; 1.6689x over previous
#include <cuda_runtime.h>
#include <cuda_bf16.h>
#include <math_constants.h>
#include <cstdint>

#define B_ 2
#define T_ 2048
#define E_ 2048
#define H_ 32
#define D_ 64
#define M_ (B_ * T_)
#define SCALING 0.125f

// ---------------- scratch (__device__ globals; allocation-free rule) --------
__device__ __nv_bfloat16 g_Ahi[M_ * E_];   // split of X; later ctx (attn output)
__device__ __nv_bfloat16 g_Alo[M_ * E_];
__device__ __nv_bfloat16 g_Whi[E_ * E_];   // split of current weight
__device__ __nv_bfloat16 g_Wlo[E_ * E_];
__device__ __nv_bfloat16 g_Qhi[M_ * E_];
__device__ __nv_bfloat16 g_Qlo[M_ * E_];
__device__ __nv_bfloat16 g_Khi[M_ * E_];
__device__ __nv_bfloat16 g_Klo[M_ * E_];
__device__ __nv_bfloat16 g_Vhi[M_ * E_];
__device__ __nv_bfloat16 g_Vlo[M_ * E_];

// ---------------- helpers ---------------------------------------------------
__device__ __forceinline__ uint32_t smem_u32(const void* p) {
    uint32_t a;
    asm("{ .reg .u64 t; cvta.to.shared.u64 t, %1; cvt.u32.u64 %0, t; }" : "=r"(a) : "l"(p));
    return a;
}
__device__ __forceinline__ void cp16(uint32_t dst, const void* src) {
    asm volatile("cp.async.cg.shared.global [%0], [%1], 16;" :: "r"(dst), "l"(src));
}
__device__ __forceinline__ void cp_commit() {
    asm volatile("cp.async.commit_group;" ::: "memory");
}
template <int N>
__device__ __forceinline__ void cp_wait() {
    asm volatile("cp.async.wait_group %0;" :: "n"(N) : "memory");
}
__device__ __forceinline__ void ldm_x4(uint32_t* d, uint32_t addr) {
    asm volatile("ldmatrix.sync.aligned.m8n8.x4.shared.b16 {%0,%1,%2,%3}, [%4];"
                 : "=r"(d[0]), "=r"(d[1]), "=r"(d[2]), "=r"(d[3]) : "r"(addr));
}
__device__ __forceinline__ void ldm_x4_t(uint32_t* d, uint32_t addr) {
    asm volatile("ldmatrix.sync.aligned.m8n8.x4.trans.shared.b16 {%0,%1,%2,%3}, [%4];"
                 : "=r"(d[0]), "=r"(d[1]), "=r"(d[2]), "=r"(d[3]) : "r"(addr));
}
__device__ __forceinline__ void mma16816(float* c, const uint32_t* a, uint32_t b0, uint32_t b1) {
    asm volatile("mma.sync.aligned.m16n8k16.row.col.f32.bf16.bf16.f32 "
                 "{%0,%1,%2,%3}, {%4,%5,%6,%7}, {%8,%9}, {%0,%1,%2,%3};"
                 : "+f"(c[0]), "+f"(c[1]), "+f"(c[2]), "+f"(c[3])
                 : "r"(a[0]), "r"(a[1]), "r"(a[2]), "r"(a[3]), "r"(b0), "r"(b1));
}
// pack {low=lo_elem, high=hi_elem} as bf16x2 (cvt.bf16x2 takes (hi, lo))
__device__ __forceinline__ uint32_t pack_bf16(float lo, float hi) {
    uint32_t r;
    asm("cvt.rn.bf16x2.f32 %0, %1, %2;" : "=r"(r) : "f"(hi), "f"(lo));
    return r;
}
// split pair (a,b) into hi/lo bf16x2 words
__device__ __forceinline__ void split2(float a, float b, uint32_t& hw, uint32_t& lw) {
    hw = pack_bf16(a, b);
    float ha = __uint_as_float(hw << 16);
    float hb = __uint_as_float(hw & 0xffff0000u);
    lw = pack_bf16(a - ha, b - hb);
}

// swizzle for 32-col (64B-row) tiles: 4 chunks of 16B
__device__ __forceinline__ uint32_t tile_off(int r, int c) {
    return (uint32_t)(r * 64 + ((c ^ ((r >> 1) & 3)) << 4));
}
// swizzle for 64-col (128B-row) tiles: 8 chunks of 16B
__device__ __forceinline__ uint32_t toff128(int r, int c) {
    return (uint32_t)(r * 128 + ((c ^ (r & 7)) << 4));
}

// ---------------------------------------------------------------------------
// split x (fp32) -> hi + lo (bf16 each)
// ---------------------------------------------------------------------------
__global__ __launch_bounds__(256) void split_fp32(
    const float* __restrict__ x, __nv_bfloat16* __restrict__ hi,
    __nv_bfloat16* __restrict__ lo, int n4)
{
    int i = blockIdx.x * 256 + threadIdx.x;
    if (i >= n4) return;
    float4 v = ((const float4*)x)[i];
    uint32_t h0, l0, h1, l1;
    split2(v.x, v.y, h0, l0);
    split2(v.z, v.w, h1, l1);
    ((uint2*)hi)[i] = make_uint2(h0, h1);
    ((uint2*)lo)[i] = make_uint2(l0, l1);
}

// ---------------------------------------------------------------------------
// bf16x3 split GEMM: C = alpha*(A@W^T + bias). Optionally writes split bf16
// output (Ohi/Olo) instead of fp32 C.
// ---------------------------------------------------------------------------
#define STAGE 32768
#define SMEM_GEMM (2 * STAGE)
#define NCHUNK (E_ / 32)

__global__ __launch_bounds__(256, 1) void gemm_tc(
    const __nv_bfloat16* __restrict__ Ahi, const __nv_bfloat16* __restrict__ Alo,
    const __nv_bfloat16* __restrict__ Whi, const __nv_bfloat16* __restrict__ Wlo,
    const float* __restrict__ bias, float* __restrict__ C,
    __nv_bfloat16* __restrict__ Ohi, __nv_bfloat16* __restrict__ Olo, float alpha)
{
    extern __shared__ __align__(1024) char smem[];
    const uint32_t su = smem_u32(smem);
    const int tid = threadIdx.x, wid = tid >> 5, lane = tid & 31;
    const int brow = blockIdx.y * 128, bcol = blockIdx.x * 128;
    const int wm = wid & 3;
    const int wn = wid >> 2;

    float acc[2][8][4];
#pragma unroll
    for (int mt = 0; mt < 2; mt++)
#pragma unroll
        for (int j = 0; j < 8; j++)
#pragma unroll
            for (int q = 0; q < 4; q++) acc[mt][j][q] = 0.f;

    auto load_chunk = [&](int k0, int s) {
        const uint32_t base = su + s * STAGE;
#pragma unroll
        for (int it = 0; it < 2; it++) {
            int idx = tid + it * 256;
            int r = idx >> 2, c = idx & 3;
            uint32_t off = tile_off(r, c);
            size_t ga = (size_t)(brow + r) * E_ + k0 + c * 8;
            size_t gw = (size_t)(bcol + r) * E_ + k0 + c * 8;
            cp16(base +         off, Ahi + ga);
            cp16(base +  8192 + off, Alo + ga);
            cp16(base + 16384 + off, Whi + gw);
            cp16(base + 24576 + off, Wlo + gw);
        }
    };

    load_chunk(0, 0);
    cp_commit();

    for (int k = 0; k < NCHUNK; k++) {
        const int s = k & 1;
        if (k + 1 < NCHUNK) {
            load_chunk((k + 1) * 32, s ^ 1);
            cp_commit();
            cp_wait<1>();
        } else {
            cp_wait<0>();
        }
        __syncthreads();

        const uint32_t bA_hi = su + s * STAGE;
        const uint32_t bA_lo = bA_hi + 8192;
        const uint32_t bW_hi = bA_hi + 16384;
        const uint32_t bW_lo = bA_hi + 24576;

#pragma unroll
        for (int ks = 0; ks < 2; ks++) {
            const int cc = ks * 2 + (lane >> 4);
            uint32_t ah[2][4], al[2][4];
#pragma unroll
            for (int mt = 0; mt < 2; mt++) {
                const int r = wm * 32 + mt * 16 + (lane & 15);
                const uint32_t off = tile_off(r, cc);
                ldm_x4(ah[mt], bA_hi + off);
                ldm_x4(al[mt], bA_lo + off);
            }
            uint32_t bh[4][4], bl[4][4];
#pragma unroll
            for (int nb = 0; nb < 4; nb++) {
                const int r = wn * 64 + nb * 16 + (lane & 15);
                const uint32_t off = tile_off(r, cc);
                ldm_x4(bh[nb], bW_hi + off);
                ldm_x4(bl[nb], bW_lo + off);
            }
#pragma unroll
            for (int mt = 0; mt < 2; mt++)
#pragma unroll
                for (int j = 0; j < 8; j++) {
                    const int nb = j >> 1, sel = j & 1;
                    mma16816(acc[mt][j], ah[mt], bh[nb][sel], bh[nb][sel + 2]);
                    mma16816(acc[mt][j], ah[mt], bl[nb][sel], bl[nb][sel + 2]);
                    mma16816(acc[mt][j], al[mt], bh[nb][sel], bh[nb][sel + 2]);
                }
        }
        __syncthreads();
    }

#pragma unroll
    for (int mt = 0; mt < 2; mt++) {
        const int r0 = brow + wm * 32 + mt * 16 + (lane >> 2);
#pragma unroll
        for (int j = 0; j < 8; j++) {
            const int col = bcol + wn * 64 + j * 8 + (lane & 3) * 2;
            const float bx = bias[col], by = bias[col + 1];
            float v00 = alpha * (acc[mt][j][0] + bx);
            float v01 = alpha * (acc[mt][j][1] + by);
            float v10 = alpha * (acc[mt][j][2] + bx);
            float v11 = alpha * (acc[mt][j][3] + by);
            if (Ohi) {
                uint32_t hw, lw;
                split2(v00, v01, hw, lw);
                *(uint32_t*)&Ohi[(size_t)r0 * E_ + col] = hw;
                *(uint32_t*)&Olo[(size_t)r0 * E_ + col] = lw;
                split2(v10, v11, hw, lw);
                *(uint32_t*)&Ohi[(size_t)(r0 + 8) * E_ + col] = hw;
                *(uint32_t*)&Olo[(size_t)(r0 + 8) * E_ + col] = lw;
            } else {
                *(float2*)&C[(size_t)r0 * E_ + col]       = make_float2(v00, v01);
                *(float2*)&C[(size_t)(r0 + 8) * E_ + col] = make_float2(v10, v11);
            }
        }
    }
}

// ---------------------------------------------------------------------------
// Tensor-core flash attention (bf16x3 scores, split-P x split-V PV).
// CTA = (b,h,64-row q tile), 4 warps x 16 rows. Output: ctx split hi/lo.
// smem: Qhi 8K | Qlo 8K | 2 stages x (Khi|Klo|Vhi|Vlo 8K each) = 80KB
// ---------------------------------------------------------------------------
#define AT_STAGE 32768
#define SMEM_ATTN (16384 + 2 * AT_STAGE)

__global__ __launch_bounds__(128, 1) void attn_tc(
    const __nv_bfloat16* __restrict__ Qhi, const __nv_bfloat16* __restrict__ Qlo,
    const __nv_bfloat16* __restrict__ Khi, const __nv_bfloat16* __restrict__ Klo,
    const __nv_bfloat16* __restrict__ Vhi, const __nv_bfloat16* __restrict__ Vlo,
    __nv_bfloat16* __restrict__ Chi, __nv_bfloat16* __restrict__ Clo)
{
    extern __shared__ __align__(1024) char smem[];
    const uint32_t su = smem_u32(smem);
    const int tid = threadIdx.x, w = tid >> 5, lane = tid & 31;
    const int qt = gridDim.x - 1 - blockIdx.x;    // heavy tiles first
    const int bh = blockIdx.y;
    const int b = bh >> 5, h = bh & 31;

    const size_t rowQ0 = (size_t)(b * T_ + qt * 64);
    const size_t rowK0 = (size_t)(b * T_);
    const int hoff = h * 64;

    // ---- async fills -------------------------------------------------------
    auto load_q = [&]() {
#pragma unroll
        for (int it = 0; it < 4; it++) {
            int idx = tid + it * 128;            // 0..511
            int r = idx >> 3, c = idx & 7;
            uint32_t off = toff128(r, c);
            size_t g = (rowQ0 + r) * E_ + hoff + c * 8;
            cp16(su +        off, Qhi + g);
            cp16(su + 8192 + off, Qlo + g);
        }
    };
    auto load_kv = [&](int jt, int s) {
        const uint32_t base = su + 16384 + s * AT_STAGE;
#pragma unroll
        for (int it = 0; it < 4; it++) {
            int idx = tid + it * 128;
            int r = idx >> 3, c = idx & 7;
            uint32_t off = toff128(r, c);
            size_t g = (rowK0 + jt * 64 + r) * E_ + hoff + c * 8;
            cp16(base +         off, Khi + g);
            cp16(base +  8192 + off, Klo + g);
            cp16(base + 16384 + off, Vhi + g);
            cp16(base + 24576 + off, Vlo + g);
        }
    };

    load_q();
    load_kv(0, 0);
    cp_commit();
    cp_wait<0>();
    __syncthreads();

    // ---- Q fragments (persistent) -----------------------------------------
    uint32_t qh[4][4], ql[4][4];
#pragma unroll
    for (int ks = 0; ks < 4; ks++) {
        const uint32_t off = toff128(16 * w + (lane & 15), ks * 2 + (lane >> 4));
        ldm_x4(qh[ks], su + off);
        ldm_x4(ql[ks], su + 8192 + off);
    }

    float oc[8][4];
#pragma unroll
    for (int nb = 0; nb < 8; nb++)
#pragma unroll
        for (int q = 0; q < 4; q++) oc[nb][q] = 0.f;
    float mrow0 = -CUDART_INF_F, mrow1 = -CUDART_INF_F;
    float lrow0 = 0.f, lrow1 = 0.f;

    for (int jt = 0; jt <= qt; jt++) {
        const int s = jt & 1;
        if (jt + 1 <= qt) {
            load_kv(jt + 1, s ^ 1);
            cp_commit();
            cp_wait<1>();
        } else {
            cp_wait<0>();
        }
        __syncthreads();

        const uint32_t bK_hi = su + 16384 + s * AT_STAGE;
        const uint32_t bK_lo = bK_hi + 8192;
        const uint32_t bV_hi = bK_hi + 16384;
        const uint32_t bV_lo = bK_hi + 24576;

        // ---- scores S = Q K^T (bf16x3) ------------------------------------
        float sc[8][4];
#pragma unroll
        for (int nb = 0; nb < 8; nb++)
#pragma unroll
            for (int q = 0; q < 4; q++) sc[nb][q] = 0.f;
#pragma unroll
        for (int ks = 0; ks < 4; ks++) {
            const int cc = ks * 2 + (lane >> 4);
#pragma unroll
            for (int nbp = 0; nbp < 4; nbp++) {
                uint32_t kh[4], kl[4];
                const uint32_t off = toff128(nbp * 16 + (lane & 15), cc);
                ldm_x4(kh, bK_hi + off);
                ldm_x4(kl, bK_lo + off);
                mma16816(sc[2 * nbp],     qh[ks], kh[0], kh[2]);
                mma16816(sc[2 * nbp],     qh[ks], kl[0], kl[2]);
                mma16816(sc[2 * nbp],     ql[ks], kh[0], kh[2]);
                mma16816(sc[2 * nbp + 1], qh[ks], kh[1], kh[3]);
                mma16816(sc[2 * nbp + 1], qh[ks], kl[1], kl[3]);
                mma16816(sc[2 * nbp + 1], ql[ks], kh[1], kh[3]);
            }
        }

        // ---- causal mask (diagonal tile only) -----------------------------
        if (jt == qt) {
            const int r0 = 16 * w + (lane >> 2);
#pragma unroll
            for (int nb = 0; nb < 8; nb++) {
                const int c0 = 8 * nb + 2 * (lane & 3);
                if (c0 > r0)     sc[nb][0] = -CUDART_INF_F;
                if (c0 + 1 > r0) sc[nb][1] = -CUDART_INF_F;
                if (c0 > r0 + 8)     sc[nb][2] = -CUDART_INF_F;
                if (c0 + 1 > r0 + 8) sc[nb][3] = -CUDART_INF_F;
            }
        }

        // ---- online softmax ----------------------------------------------
        float tm0 = -CUDART_INF_F, tm1 = -CUDART_INF_F;
#pragma unroll
        for (int nb = 0; nb < 8; nb++) {
            tm0 = fmaxf(tm0, fmaxf(sc[nb][0], sc[nb][1]));
            tm1 = fmaxf(tm1, fmaxf(sc[nb][2], sc[nb][3]));
        }
        tm0 = fmaxf(tm0, __shfl_xor_sync(0xffffffffu, tm0, 1));
        tm0 = fmaxf(tm0, __shfl_xor_sync(0xffffffffu, tm0, 2));
        tm1 = fmaxf(tm1, __shfl_xor_sync(0xffffffffu, tm1, 1));
        tm1 = fmaxf(tm1, __shfl_xor_sync(0xffffffffu, tm1, 2));
        const float mn0 = fmaxf(mrow0, tm0), mn1 = fmaxf(mrow1, tm1);
        const float scl0 = __expf(mrow0 - mn0), scl1 = __expf(mrow1 - mn1);
        float ls0 = 0.f, ls1 = 0.f;
#pragma unroll
        for (int nb = 0; nb < 8; nb++) {
            sc[nb][0] = __expf(sc[nb][0] - mn0);
            sc[nb][1] = __expf(sc[nb][1] - mn0);
            sc[nb][2] = __expf(sc[nb][2] - mn1);
            sc[nb][3] = __expf(sc[nb][3] - mn1);
            ls0 += sc[nb][0] + sc[nb][1];
            ls1 += sc[nb][2] + sc[nb][3];
        }
        ls0 += __shfl_xor_sync(0xffffffffu, ls0, 1);
        ls0 += __shfl_xor_sync(0xffffffffu, ls0, 2);
        ls1 += __shfl_xor_sync(0xffffffffu, ls1, 1);
        ls1 += __shfl_xor_sync(0xffffffffu, ls1, 2);
        lrow0 = lrow0 * scl0 + ls0;
        lrow1 = lrow1 * scl1 + ls1;
        mrow0 = mn0; mrow1 = mn1;
#pragma unroll
        for (int nb = 0; nb < 8; nb++) {
            oc[nb][0] *= scl0; oc[nb][1] *= scl0;
            oc[nb][2] *= scl1; oc[nb][3] *= scl1;
        }

        // ---- repack P into A-fragments (split hi/lo) ----------------------
        uint32_t aph[4][4], apl[4][4];
#pragma unroll
        for (int ks = 0; ks < 4; ks++) {
            split2(sc[2 * ks][0],     sc[2 * ks][1],     aph[ks][0], apl[ks][0]);
            split2(sc[2 * ks][2],     sc[2 * ks][3],     aph[ks][1], apl[ks][1]);
            split2(sc[2 * ks + 1][0], sc[2 * ks + 1][1], aph[ks][2], apl[ks][2]);
            split2(sc[2 * ks + 1][2], sc[2 * ks + 1][3], aph[ks][3], apl[ks][3]);
        }

        // ---- O += P V (trans-ldmatrix on V) -------------------------------
#pragma unroll
        for (int ks = 0; ks < 4; ks++) {
#pragma unroll
            for (int dbp = 0; dbp < 4; dbp++) {
                uint32_t vh[4], vl[4];
                const uint32_t off = toff128(16 * ks + (lane & 15), dbp * 2 + (lane >> 4));
                ldm_x4_t(vh, bV_hi + off);
                ldm_x4_t(vl, bV_lo + off);
                mma16816(oc[2 * dbp],     aph[ks], vh[0], vh[1]);
                mma16816(oc[2 * dbp],     aph[ks], vl[0], vl[1]);
                mma16816(oc[2 * dbp],     apl[ks], vh[0], vh[1]);
                mma16816(oc[2 * dbp + 1], aph[ks], vh[2], vh[3]);
                mma16816(oc[2 * dbp + 1], aph[ks], vl[2], vl[3]);
                mma16816(oc[2 * dbp + 1], apl[ks], vh[2], vh[3]);
            }
        }
        __syncthreads();
    }

    // ---- epilogue: ctx = O / l, write split hi/lo --------------------------
    const float inv0 = 1.f / lrow0, inv1 = 1.f / lrow1;
    const size_t r0 = rowQ0 + 16 * w + (lane >> 2);
#pragma unroll
    for (int nb = 0; nb < 8; nb++) {
        const int col = hoff + 8 * nb + 2 * (lane & 3);
        uint32_t hw, lw;
        split2(oc[nb][0] * inv0, oc[nb][1] * inv0, hw, lw);
        *(uint32_t*)&Chi[r0 * E_ + col] = hw;
        *(uint32_t*)&Clo[r0 * E_ + col] = lw;
        split2(oc[nb][2] * inv1, oc[nb][3] * inv1, hw, lw);
        *(uint32_t*)&Chi[(r0 + 8) * E_ + col] = hw;
        *(uint32_t*)&Clo[(r0 + 8) * E_ + col] = lw;
    }
}

// ---------------------------------------------------------------------------
extern "C" void kernel_launch(void* const* d_in, const int* in_sizes, int n_in,
                              void* d_out, int out_size)
{
    const float* X  = (const float*)d_in[0];
    const float* Wq = (const float*)d_in[1];
    const float* bq = (const float*)d_in[2];
    const float* Wk = (const float*)d_in[3];
    const float* bk = (const float*)d_in[4];
    const float* Wv = (const float*)d_in[5];
    const float* bv = (const float*)d_in[6];
    const float* Wo = (const float*)d_in[7];
    const float* bo = (const float*)d_in[8];
    float* out = (float*)d_out;

    __nv_bfloat16 *Ahi, *Alo, *Whi, *Wlo, *Qhi, *Qlo, *Khi, *Klo, *Vhi, *Vlo;
    cudaGetSymbolAddress((void**)&Ahi, g_Ahi);
    cudaGetSymbolAddress((void**)&Alo, g_Alo);
    cudaGetSymbolAddress((void**)&Whi, g_Whi);
    cudaGetSymbolAddress((void**)&Wlo, g_Wlo);
    cudaGetSymbolAddress((void**)&Qhi, g_Qhi);
    cudaGetSymbolAddress((void**)&Qlo, g_Qlo);
    cudaGetSymbolAddress((void**)&Khi, g_Khi);
    cudaGetSymbolAddress((void**)&Klo, g_Klo);
    cudaGetSymbolAddress((void**)&Vhi, g_Vhi);
    cudaGetSymbolAddress((void**)&Vlo, g_Vlo);

    cudaFuncSetAttribute(gemm_tc, cudaFuncAttributeMaxDynamicSharedMemorySize, SMEM_GEMM);
    cudaFuncSetAttribute(attn_tc, cudaFuncAttributeMaxDynamicSharedMemorySize, SMEM_ATTN);

    const int nX4 = (M_ * E_) / 4;
    const int nW4 = (E_ * E_) / 4;
    dim3 gg(E_ / 128, M_ / 128);

    split_fp32<<<(nX4 + 255) / 256, 256>>>(X, Ahi, Alo, nX4);

    split_fp32<<<(nW4 + 255) / 256, 256>>>(Wq, Whi, Wlo, nW4);
    gemm_tc<<<gg, 256, SMEM_GEMM>>>(Ahi, Alo, Whi, Wlo, bq, nullptr, Qhi, Qlo, SCALING);

    split_fp32<<<(nW4 + 255) / 256, 256>>>(Wk, Whi, Wlo, nW4);
    gemm_tc<<<gg, 256, SMEM_GEMM>>>(Ahi, Alo, Whi, Wlo, bk, nullptr, Khi, Klo, 1.0f);

    split_fp32<<<(nW4 + 255) / 256, 256>>>(Wv, Whi, Wlo, nW4);
    gemm_tc<<<gg, 256, SMEM_GEMM>>>(Ahi, Alo, Whi, Wlo, bv, nullptr, Vhi, Vlo, 1.0f);

    dim3 ag(T_ / 64, B_ * H_);
    attn_tc<<<ag, 128, SMEM_ATTN>>>(Qhi, Qlo, Khi, Klo, Vhi, Vlo, Ahi, Alo);

    split_fp32<<<(nW4 + 255) / 256, 256>>>(Wo, Whi, Wlo, nW4);
    gemm_tc<<<gg, 256, SMEM_GEMM>>>(Ahi, Alo, Whi, Wlo, bo, out, nullptr, nullptr, 1.0f);
}

// round 7
// speedup vs baseline: 3.1364x; 1.0847x over previous
#include <cuda_runtime.h>
#include <cuda_bf16.h>
#include <math_constants.h>
#include <cstdint>

#define B_ 2
#define T_ 2048
#define E_ 2048
#define H_ 32
#define D_ 64
#define M_ (B_ * T_)
#define SCALING 0.125f

// ---------------- scratch (__device__ globals; allocation-free rule) --------
__device__ __nv_bfloat16 g_Ahi[M_ * E_];   // split of X; later ctx (attn output)
__device__ __nv_bfloat16 g_Alo[M_ * E_];
__device__ __nv_bfloat16 g_Whi[4][E_ * E_];  // q,k,v,o weight splits
__device__ __nv_bfloat16 g_Wlo[4][E_ * E_];
__device__ __nv_bfloat16 g_Qhi[M_ * E_];
__device__ __nv_bfloat16 g_Qlo[M_ * E_];
__device__ __nv_bfloat16 g_Khi[M_ * E_];
__device__ __nv_bfloat16 g_Klo[M_ * E_];
__device__ __nv_bfloat16 g_Vhi[M_ * E_];
__device__ __nv_bfloat16 g_Vlo[M_ * E_];

// ---------------- helpers ---------------------------------------------------
__device__ __forceinline__ uint32_t smem_u32(const void* p) {
    uint32_t a;
    asm("{ .reg .u64 t; cvta.to.shared.u64 t, %1; cvt.u32.u64 %0, t; }" : "=r"(a) : "l"(p));
    return a;
}
__device__ __forceinline__ void cp16(uint32_t dst, const void* src) {
    asm volatile("cp.async.cg.shared.global [%0], [%1], 16;" :: "r"(dst), "l"(src));
}
__device__ __forceinline__ void cp_commit() {
    asm volatile("cp.async.commit_group;" ::: "memory");
}
template <int N>
__device__ __forceinline__ void cp_wait() {
    asm volatile("cp.async.wait_group %0;" :: "n"(N) : "memory");
}
__device__ __forceinline__ void ldm_x4(uint32_t* d, uint32_t addr) {
    asm volatile("ldmatrix.sync.aligned.m8n8.x4.shared.b16 {%0,%1,%2,%3}, [%4];"
                 : "=r"(d[0]), "=r"(d[1]), "=r"(d[2]), "=r"(d[3]) : "r"(addr));
}
__device__ __forceinline__ void ldm_x4_t(uint32_t* d, uint32_t addr) {
    asm volatile("ldmatrix.sync.aligned.m8n8.x4.trans.shared.b16 {%0,%1,%2,%3}, [%4];"
                 : "=r"(d[0]), "=r"(d[1]), "=r"(d[2]), "=r"(d[3]) : "r"(addr));
}
__device__ __forceinline__ void mma16816(float* c, const uint32_t* a, uint32_t b0, uint32_t b1) {
    asm volatile("mma.sync.aligned.m16n8k16.row.col.f32.bf16.bf16.f32 "
                 "{%0,%1,%2,%3}, {%4,%5,%6,%7}, {%8,%9}, {%0,%1,%2,%3};"
                 : "+f"(c[0]), "+f"(c[1]), "+f"(c[2]), "+f"(c[3])
                 : "r"(a[0]), "r"(a[1]), "r"(a[2]), "r"(a[3]), "r"(b0), "r"(b1));
}
__device__ __forceinline__ uint32_t pack_bf16(float lo, float hi) {
    uint32_t r;
    asm("cvt.rn.bf16x2.f32 %0, %1, %2;" : "=r"(r) : "f"(hi), "f"(lo));
    return r;
}
__device__ __forceinline__ void split2(float a, float b, uint32_t& hw, uint32_t& lw) {
    hw = pack_bf16(a, b);
    float ha = __uint_as_float(hw << 16);
    float hb = __uint_as_float(hw & 0xffff0000u);
    lw = pack_bf16(a - ha, b - hb);
}
// swizzle for 64-col (128B-row) bf16 tiles: 8 chunks of 16B per row
__device__ __forceinline__ uint32_t toff128(int r, int c) {
    return (uint32_t)(r * 128 + ((c ^ (r & 7)) << 4));
}

// ---------------------------------------------------------------------------
// splits
// ---------------------------------------------------------------------------
__global__ __launch_bounds__(256) void split_fp32(
    const float* __restrict__ x, __nv_bfloat16* __restrict__ hi,
    __nv_bfloat16* __restrict__ lo, int n4)
{
    int i = blockIdx.x * 256 + threadIdx.x;
    if (i >= n4) return;
    float4 v = ((const float4*)x)[i];
    uint32_t h0, l0, h1, l1;
    split2(v.x, v.y, h0, l0);
    split2(v.z, v.w, h1, l1);
    ((uint2*)hi)[i] = make_uint2(h0, h1);
    ((uint2*)lo)[i] = make_uint2(l0, l1);
}

struct SplitJobs {
    const float* src[4];
    __nv_bfloat16* hi[4];
    __nv_bfloat16* lo[4];
};
__global__ __launch_bounds__(256) void split_weights(SplitJobs jobs, int n4)
{
    int i = blockIdx.x * 256 + threadIdx.x;
    if (i >= n4) return;
    const int w = blockIdx.y;
    float4 v = ((const float4*)jobs.src[w])[i];
    uint32_t h0, l0, h1, l1;
    split2(v.x, v.y, h0, l0);
    split2(v.z, v.w, h1, l1);
    ((uint2*)jobs.hi[w])[i] = make_uint2(h0, h1);
    ((uint2*)jobs.lo[w])[i] = make_uint2(l0, l1);
}

// ---------------------------------------------------------------------------
// bf16x3 split GEMM, BK=64, 3-stage cp.async pipeline, one sync per chunk.
// grid.z = batched jobs (shared A). Stage 64KB: Ahi|Alo|Whi|Wlo 16KB each.
// ---------------------------------------------------------------------------
#define GSTAGE 65536
#define SMEM_GEMM (3 * GSTAGE)
#define NCH64 (E_ / 64)

struct GemmJobs {
    const __nv_bfloat16* Whi[3];
    const __nv_bfloat16* Wlo[3];
    const float* bias[3];
    __nv_bfloat16* Ohi[3];
    __nv_bfloat16* Olo[3];
    float* C[3];
    float alpha[3];
};

__global__ __launch_bounds__(256, 1) void gemm_tc(
    const __nv_bfloat16* __restrict__ Ahi, const __nv_bfloat16* __restrict__ Alo,
    GemmJobs jobs)
{
    extern __shared__ __align__(1024) char smem[];
    const uint32_t su = smem_u32(smem);
    const int tid = threadIdx.x, wid = tid >> 5, lane = tid & 31;
    const int brow = blockIdx.y * 128, bcol = blockIdx.x * 128;
    const int jz = blockIdx.z;
    const __nv_bfloat16* Whi = jobs.Whi[jz];
    const __nv_bfloat16* Wlo = jobs.Wlo[jz];
    const int wm = wid & 3;
    const int wn = wid >> 2;

    float acc[2][8][4];
#pragma unroll
    for (int mt = 0; mt < 2; mt++)
#pragma unroll
        for (int j = 0; j < 8; j++)
#pragma unroll
            for (int q = 0; q < 4; q++) acc[mt][j][q] = 0.f;

    auto load_chunk = [&](int k0, int s) {
        const uint32_t base = su + s * GSTAGE;
#pragma unroll
        for (int it = 0; it < 4; it++) {
            int idx = tid + it * 256;            // 0..1023: 128 rows x 8 chunks
            int r = idx >> 3, c = idx & 7;
            uint32_t off = toff128(r, c);
            size_t ga = (size_t)(brow + r) * E_ + k0 + c * 8;
            size_t gw = (size_t)(bcol + r) * E_ + k0 + c * 8;
            cp16(base +         off, Ahi + ga);
            cp16(base + 16384 + off, Alo + ga);
            cp16(base + 32768 + off, Whi + gw);
            cp16(base + 49152 + off, Wlo + gw);
        }
        cp_commit();
    };

    load_chunk(0, 0);
    load_chunk(64, 1);

    for (int k = 0; k < NCH64; k++) {
        if (k + 1 < NCH64) { cp_wait<1>(); } else { cp_wait<0>(); }
        __syncthreads();
        if (k + 2 < NCH64) load_chunk((k + 2) * 64, (k + 2) % 3);

        const uint32_t bA_hi = su + (k % 3) * GSTAGE;
        const uint32_t bA_lo = bA_hi + 16384;
        const uint32_t bW_hi = bA_hi + 32768;
        const uint32_t bW_lo = bA_hi + 49152;

#pragma unroll
        for (int ks = 0; ks < 4; ks++) {
            const int cc = ks * 2 + (lane >> 4);
            uint32_t ah[2][4], al[2][4];
#pragma unroll
            for (int mt = 0; mt < 2; mt++) {
                const uint32_t off = toff128(wm * 32 + mt * 16 + (lane & 15), cc);
                ldm_x4(ah[mt], bA_hi + off);
                ldm_x4(al[mt], bA_lo + off);
            }
            uint32_t bh[4][4], bl[4][4];
#pragma unroll
            for (int nb = 0; nb < 4; nb++) {
                const uint32_t off = toff128(wn * 64 + nb * 16 + (lane & 15), cc);
                ldm_x4(bh[nb], bW_hi + off);
                ldm_x4(bl[nb], bW_lo + off);
            }
#pragma unroll
            for (int mt = 0; mt < 2; mt++)
#pragma unroll
                for (int j = 0; j < 8; j++) {
                    const int nb = j >> 1, sel = j & 1;
                    mma16816(acc[mt][j], ah[mt], bh[nb][sel], bh[nb][sel + 2]);
                    mma16816(acc[mt][j], ah[mt], bl[nb][sel], bl[nb][sel + 2]);
                    mma16816(acc[mt][j], al[mt], bh[nb][sel], bh[nb][sel + 2]);
                }
        }
        __syncthreads();
    }

    const float alpha = jobs.alpha[jz];
    const float* bias = jobs.bias[jz];
    __nv_bfloat16* Ohi = jobs.Ohi[jz];
    __nv_bfloat16* Olo = jobs.Olo[jz];
    float* C = jobs.C[jz];
#pragma unroll
    for (int mt = 0; mt < 2; mt++) {
        const int r0 = brow + wm * 32 + mt * 16 + (lane >> 2);
#pragma unroll
        for (int j = 0; j < 8; j++) {
            const int col = bcol + wn * 64 + j * 8 + (lane & 3) * 2;
            const float bx = bias[col], by = bias[col + 1];
            float v00 = alpha * (acc[mt][j][0] + bx);
            float v01 = alpha * (acc[mt][j][1] + by);
            float v10 = alpha * (acc[mt][j][2] + bx);
            float v11 = alpha * (acc[mt][j][3] + by);
            if (Ohi) {
                uint32_t hw, lw;
                split2(v00, v01, hw, lw);
                *(uint32_t*)&Ohi[(size_t)r0 * E_ + col] = hw;
                *(uint32_t*)&Olo[(size_t)r0 * E_ + col] = lw;
                split2(v10, v11, hw, lw);
                *(uint32_t*)&Ohi[(size_t)(r0 + 8) * E_ + col] = hw;
                *(uint32_t*)&Olo[(size_t)(r0 + 8) * E_ + col] = lw;
            } else {
                *(float2*)&C[(size_t)r0 * E_ + col]       = make_float2(v00, v01);
                *(float2*)&C[(size_t)(r0 + 8) * E_ + col] = make_float2(v10, v11);
            }
        }
    }
}

// ---------------------------------------------------------------------------
// Tensor-core flash attention (unchanged from R6: proven rel_err 2.6e-5)
// ---------------------------------------------------------------------------
#define AT_STAGE 32768
#define SMEM_ATTN (16384 + 2 * AT_STAGE)

__global__ __launch_bounds__(128, 1) void attn_tc(
    const __nv_bfloat16* __restrict__ Qhi, const __nv_bfloat16* __restrict__ Qlo,
    const __nv_bfloat16* __restrict__ Khi, const __nv_bfloat16* __restrict__ Klo,
    const __nv_bfloat16* __restrict__ Vhi, const __nv_bfloat16* __restrict__ Vlo,
    __nv_bfloat16* __restrict__ Chi, __nv_bfloat16* __restrict__ Clo)
{
    extern __shared__ __align__(1024) char smem[];
    const uint32_t su = smem_u32(smem);
    const int tid = threadIdx.x, w = tid >> 5, lane = tid & 31;
    const int qt = gridDim.x - 1 - blockIdx.x;
    const int bh = blockIdx.y;
    const int b = bh >> 5, h = bh & 31;

    const size_t rowQ0 = (size_t)(b * T_ + qt * 64);
    const size_t rowK0 = (size_t)(b * T_);
    const int hoff = h * 64;

    auto load_q = [&]() {
#pragma unroll
        for (int it = 0; it < 4; it++) {
            int idx = tid + it * 128;
            int r = idx >> 3, c = idx & 7;
            uint32_t off = toff128(r, c);
            size_t g = (rowQ0 + r) * E_ + hoff + c * 8;
            cp16(su +        off, Qhi + g);
            cp16(su + 8192 + off, Qlo + g);
        }
    };
    auto load_kv = [&](int jt, int s) {
        const uint32_t base = su + 16384 + s * AT_STAGE;
#pragma unroll
        for (int it = 0; it < 4; it++) {
            int idx = tid + it * 128;
            int r = idx >> 3, c = idx & 7;
            uint32_t off = toff128(r, c);
            size_t g = (rowK0 + jt * 64 + r) * E_ + hoff + c * 8;
            cp16(base +         off, Khi + g);
            cp16(base +  8192 + off, Klo + g);
            cp16(base + 16384 + off, Vhi + g);
            cp16(base + 24576 + off, Vlo + g);
        }
    };

    load_q();
    load_kv(0, 0);
    cp_commit();
    cp_wait<0>();
    __syncthreads();

    uint32_t qh[4][4], ql[4][4];
#pragma unroll
    for (int ks = 0; ks < 4; ks++) {
        const uint32_t off = toff128(16 * w + (lane & 15), ks * 2 + (lane >> 4));
        ldm_x4(qh[ks], su + off);
        ldm_x4(ql[ks], su + 8192 + off);
    }

    float oc[8][4];
#pragma unroll
    for (int nb = 0; nb < 8; nb++)
#pragma unroll
        for (int q = 0; q < 4; q++) oc[nb][q] = 0.f;
    float mrow0 = -CUDART_INF_F, mrow1 = -CUDART_INF_F;
    float lrow0 = 0.f, lrow1 = 0.f;

    for (int jt = 0; jt <= qt; jt++) {
        const int s = jt & 1;
        if (jt + 1 <= qt) {
            load_kv(jt + 1, s ^ 1);
            cp_commit();
            cp_wait<1>();
        } else {
            cp_wait<0>();
        }
        __syncthreads();

        const uint32_t bK_hi = su + 16384 + s * AT_STAGE;
        const uint32_t bK_lo = bK_hi + 8192;
        const uint32_t bV_hi = bK_hi + 16384;
        const uint32_t bV_lo = bK_hi + 24576;

        float sc[8][4];
#pragma unroll
        for (int nb = 0; nb < 8; nb++)
#pragma unroll
            for (int q = 0; q < 4; q++) sc[nb][q] = 0.f;
#pragma unroll
        for (int ks = 0; ks < 4; ks++) {
            const int cc = ks * 2 + (lane >> 4);
#pragma unroll
            for (int nbp = 0; nbp < 4; nbp++) {
                uint32_t kh[4], kl[4];
                const uint32_t off = toff128(nbp * 16 + (lane & 15), cc);
                ldm_x4(kh, bK_hi + off);
                ldm_x4(kl, bK_lo + off);
                mma16816(sc[2 * nbp],     qh[ks], kh[0], kh[2]);
                mma16816(sc[2 * nbp],     qh[ks], kl[0], kl[2]);
                mma16816(sc[2 * nbp],     ql[ks], kh[0], kh[2]);
                mma16816(sc[2 * nbp + 1], qh[ks], kh[1], kh[3]);
                mma16816(sc[2 * nbp + 1], qh[ks], kl[1], kl[3]);
                mma16816(sc[2 * nbp + 1], ql[ks], kh[1], kh[3]);
            }
        }

        if (jt == qt) {
            const int r0 = 16 * w + (lane >> 2);
#pragma unroll
            for (int nb = 0; nb < 8; nb++) {
                const int c0 = 8 * nb + 2 * (lane & 3);
                if (c0 > r0)     sc[nb][0] = -CUDART_INF_F;
                if (c0 + 1 > r0) sc[nb][1] = -CUDART_INF_F;
                if (c0 > r0 + 8)     sc[nb][2] = -CUDART_INF_F;
                if (c0 + 1 > r0 + 8) sc[nb][3] = -CUDART_INF_F;
            }
        }

        float tm0 = -CUDART_INF_F, tm1 = -CUDART_INF_F;
#pragma unroll
        for (int nb = 0; nb < 8; nb++) {
            tm0 = fmaxf(tm0, fmaxf(sc[nb][0], sc[nb][1]));
            tm1 = fmaxf(tm1, fmaxf(sc[nb][2], sc[nb][3]));
        }
        tm0 = fmaxf(tm0, __shfl_xor_sync(0xffffffffu, tm0, 1));
        tm0 = fmaxf(tm0, __shfl_xor_sync(0xffffffffu, tm0, 2));
        tm1 = fmaxf(tm1, __shfl_xor_sync(0xffffffffu, tm1, 1));
        tm1 = fmaxf(tm1, __shfl_xor_sync(0xffffffffu, tm1, 2));
        const float mn0 = fmaxf(mrow0, tm0), mn1 = fmaxf(mrow1, tm1);
        const float scl0 = __expf(mrow0 - mn0), scl1 = __expf(mrow1 - mn1);
        float ls0 = 0.f, ls1 = 0.f;
#pragma unroll
        for (int nb = 0; nb < 8; nb++) {
            sc[nb][0] = __expf(sc[nb][0] - mn0);
            sc[nb][1] = __expf(sc[nb][1] - mn0);
            sc[nb][2] = __expf(sc[nb][2] - mn1);
            sc[nb][3] = __expf(sc[nb][3] - mn1);
            ls0 += sc[nb][0] + sc[nb][1];
            ls1 += sc[nb][2] + sc[nb][3];
        }
        ls0 += __shfl_xor_sync(0xffffffffu, ls0, 1);
        ls0 += __shfl_xor_sync(0xffffffffu, ls0, 2);
        ls1 += __shfl_xor_sync(0xffffffffu, ls1, 1);
        ls1 += __shfl_xor_sync(0xffffffffu, ls1, 2);
        lrow0 = lrow0 * scl0 + ls0;
        lrow1 = lrow1 * scl1 + ls1;
        mrow0 = mn0; mrow1 = mn1;
#pragma unroll
        for (int nb = 0; nb < 8; nb++) {
            oc[nb][0] *= scl0; oc[nb][1] *= scl0;
            oc[nb][2] *= scl1; oc[nb][3] *= scl1;
        }

        uint32_t aph[4][4], apl[4][4];
#pragma unroll
        for (int ks = 0; ks < 4; ks++) {
            split2(sc[2 * ks][0],     sc[2 * ks][1],     aph[ks][0], apl[ks][0]);
            split2(sc[2 * ks][2],     sc[2 * ks][3],     aph[ks][1], apl[ks][1]);
            split2(sc[2 * ks + 1][0], sc[2 * ks + 1][1], aph[ks][2], apl[ks][2]);
            split2(sc[2 * ks + 1][2], sc[2 * ks + 1][3], aph[ks][3], apl[ks][3]);
        }

#pragma unroll
        for (int ks = 0; ks < 4; ks++) {
#pragma unroll
            for (int dbp = 0; dbp < 4; dbp++) {
                uint32_t vh[4], vl[4];
                const uint32_t off = toff128(16 * ks + (lane & 15), dbp * 2 + (lane >> 4));
                ldm_x4_t(vh, bV_hi + off);
                ldm_x4_t(vl, bV_lo + off);
                mma16816(oc[2 * dbp],     aph[ks], vh[0], vh[1]);
                mma16816(oc[2 * dbp],     aph[ks], vl[0], vl[1]);
                mma16816(oc[2 * dbp],     apl[ks], vh[0], vh[1]);
                mma16816(oc[2 * dbp + 1], aph[ks], vh[2], vh[3]);
                mma16816(oc[2 * dbp + 1], aph[ks], vl[2], vl[3]);
                mma16816(oc[2 * dbp + 1], apl[ks], vh[2], vh[3]);
            }
        }
        __syncthreads();
    }

    const float inv0 = 1.f / lrow0, inv1 = 1.f / lrow1;
    const size_t r0 = rowQ0 + 16 * w + (lane >> 2);
#pragma unroll
    for (int nb = 0; nb < 8; nb++) {
        const int col = hoff + 8 * nb + 2 * (lane & 3);
        uint32_t hw, lw;
        split2(oc[nb][0] * inv0, oc[nb][1] * inv0, hw, lw);
        *(uint32_t*)&Chi[r0 * E_ + col] = hw;
        *(uint32_t*)&Clo[r0 * E_ + col] = lw;
        split2(oc[nb][2] * inv1, oc[nb][3] * inv1, hw, lw);
        *(uint32_t*)&Chi[(r0 + 8) * E_ + col] = hw;
        *(uint32_t*)&Clo[(r0 + 8) * E_ + col] = lw;
    }
}

// ---------------------------------------------------------------------------
extern "C" void kernel_launch(void* const* d_in, const int* in_sizes, int n_in,
                              void* d_out, int out_size)
{
    const float* X  = (const float*)d_in[0];
    const float* Wq = (const float*)d_in[1];
    const float* bq = (const float*)d_in[2];
    const float* Wk = (const float*)d_in[3];
    const float* bk = (const float*)d_in[4];
    const float* Wv = (const float*)d_in[5];
    const float* bv = (const float*)d_in[6];
    const float* Wo = (const float*)d_in[7];
    const float* bo = (const float*)d_in[8];
    float* out = (float*)d_out;

    __nv_bfloat16 *Ahi, *Alo, *Qhi, *Qlo, *Khi, *Klo, *Vhi, *Vlo;
    __nv_bfloat16 *WhiB, *WloB;
    cudaGetSymbolAddress((void**)&Ahi, g_Ahi);
    cudaGetSymbolAddress((void**)&Alo, g_Alo);
    cudaGetSymbolAddress((void**)&WhiB, g_Whi);
    cudaGetSymbolAddress((void**)&WloB, g_Wlo);
    cudaGetSymbolAddress((void**)&Qhi, g_Qhi);
    cudaGetSymbolAddress((void**)&Qlo, g_Qlo);
    cudaGetSymbolAddress((void**)&Khi, g_Khi);
    cudaGetSymbolAddress((void**)&Klo, g_Klo);
    cudaGetSymbolAddress((void**)&Vhi, g_Vhi);
    cudaGetSymbolAddress((void**)&Vlo, g_Vlo);
    const size_t WSZ = (size_t)E_ * E_;

    cudaFuncSetAttribute(gemm_tc, cudaFuncAttributeMaxDynamicSharedMemorySize, SMEM_GEMM);
    cudaFuncSetAttribute(attn_tc, cudaFuncAttributeMaxDynamicSharedMemorySize, SMEM_ATTN);

    const int nX4 = (M_ * E_) / 4;
    const int nW4 = (E_ * E_) / 4;

    // all weight splits in one launch, X split in parallel stream order
    SplitJobs sj;
    sj.src[0] = Wq; sj.src[1] = Wk; sj.src[2] = Wv; sj.src[3] = Wo;
    for (int i = 0; i < 4; i++) { sj.hi[i] = WhiB + i * WSZ; sj.lo[i] = WloB + i * WSZ; }
    split_weights<<<dim3((nW4 + 255) / 256, 4), 256>>>(sj, nW4);
    split_fp32<<<(nX4 + 255) / 256, 256>>>(X, Ahi, Alo, nX4);

    // batched Q,K,V projections
    GemmJobs qkv;
    qkv.Whi[0] = WhiB;           qkv.Wlo[0] = WloB;
    qkv.Whi[1] = WhiB + WSZ;     qkv.Wlo[1] = WloB + WSZ;
    qkv.Whi[2] = WhiB + 2 * WSZ; qkv.Wlo[2] = WloB + 2 * WSZ;
    qkv.bias[0] = bq; qkv.bias[1] = bk; qkv.bias[2] = bv;
    qkv.Ohi[0] = Qhi; qkv.Olo[0] = Qlo;
    qkv.Ohi[1] = Khi; qkv.Olo[1] = Klo;
    qkv.Ohi[2] = Vhi; qkv.Olo[2] = Vlo;
    qkv.C[0] = qkv.C[1] = qkv.C[2] = nullptr;
    qkv.alpha[0] = SCALING; qkv.alpha[1] = 1.f; qkv.alpha[2] = 1.f;
    gemm_tc<<<dim3(E_ / 128, M_ / 128, 3), 256, SMEM_GEMM>>>(Ahi, Alo, qkv);

    dim3 ag(T_ / 64, B_ * H_);
    attn_tc<<<ag, 128, SMEM_ATTN>>>(Qhi, Qlo, Khi, Klo, Vhi, Vlo, Ahi, Alo);

    // output projection (fp32 out)
    GemmJobs oj;
    oj.Whi[0] = WhiB + 3 * WSZ; oj.Wlo[0] = WloB + 3 * WSZ;
    oj.bias[0] = bo;
    oj.Ohi[0] = nullptr; oj.Olo[0] = nullptr;
    oj.C[0] = out;
    oj.alpha[0] = 1.f;
    oj.Whi[1] = oj.Whi[2] = nullptr; oj.Wlo[1] = oj.Wlo[2] = nullptr;
    oj.bias[1] = oj.bias[2] = nullptr;
    oj.Ohi[1] = oj.Ohi[2] = nullptr; oj.Olo[1] = oj.Olo[2] = nullptr;
    oj.C[1] = oj.C[2] = nullptr;
    oj.alpha[1] = oj.alpha[2] = 0.f;
    gemm_tc<<<dim3(E_ / 128, M_ / 128, 1), 256, SMEM_GEMM>>>(Ahi, Alo, oj);
}